// round 1
// baseline (speedup 1.0000x reference)
#include <cuda_runtime.h>
#include <cuda_bf16.h>
#include <cstdint>

// Problem constants
#define NBM   64      // B*M = 2*32
#define LSEQ  512
#define CDIM  512
#define NH    8
#define HD    64
#define NROWS (NBM*LSEQ)   // 32768

// Scratch: Q,K as [bm][h][l][d]; V transposed as [bm][h][d][l]
__device__ float g_q[NBM*NH*LSEQ*HD];
__device__ float g_k[NBM*NH*LSEQ*HD];
__device__ float g_v[NBM*NH*HD*LSEQ];

__device__ __forceinline__ unsigned f2tf(float f) {
    unsigned u;
    asm("cvt.rna.tf32.f32 %0, %1;" : "=r"(u) : "f"(f));
    return u;
}

__device__ __forceinline__ void mma_tf32(float* c, const unsigned* a, const unsigned* b) {
    asm("mma.sync.aligned.m16n8k8.row.col.f32.tf32.tf32.f32 "
        "{%0,%1,%2,%3}, {%4,%5,%6,%7}, {%8,%9}, {%0,%1,%2,%3};"
        : "+f"(c[0]), "+f"(c[1]), "+f"(c[2]), "+f"(c[3])
        : "r"(a[0]), "r"(a[1]), "r"(a[2]), "r"(a[3]),
          "r"(b[0]), "r"(b[1]));
}

// ---------------------------------------------------------------------------
// Kernel 1: fused QKV projection.
// Logical GEMM: X(32768 x 512) @ [Wq|Wk|Wv](512 x 1536) + bias.
// Tile: 128 rows x 64 cols per CTA, 256 threads (8 warps as 4x2, 32x32 each).
// ---------------------------------------------------------------------------
__global__ __launch_bounds__(256) void qkv_kernel(
    const float* __restrict__ x,
    const float* __restrict__ Wq, const float* __restrict__ bq,
    const float* __restrict__ Wk, const float* __restrict__ bk,
    const float* __restrict__ Wv, const float* __restrict__ bv)
{
    __shared__ unsigned Xs[128][36];  // 128 rows x 32 k, pad 4
    __shared__ unsigned Ws[32][68];   // 32 k x 64 n, pad 4

    const int nglob0 = blockIdx.x * 64;       // 0..1535
    const int mat    = nglob0 >> 9;           // 0=Q,1=K,2=V
    const int col0   = nglob0 & 511;
    const int r0     = blockIdx.y * 128;

    const float* W    = (mat == 0) ? Wq : (mat == 1) ? Wk : Wv;
    const float* bias = (mat == 0) ? bq : (mat == 1) ? bk : bv;

    const int tid  = threadIdx.x;
    const int lane = tid & 31;
    const int warp = tid >> 5;
    const int wm   = (warp >> 1) * 32;   // warp row offset in tile
    const int wn   = (warp & 1) * 32;    // warp col offset in tile
    const int g    = lane >> 2;          // group id 0..7
    const int t    = lane & 3;           // thread-in-group 0..3

    float acc[2][4][4];
    #pragma unroll
    for (int mi = 0; mi < 2; mi++)
        #pragma unroll
        for (int ni = 0; ni < 4; ni++)
            #pragma unroll
            for (int e = 0; e < 4; e++) acc[mi][ni][e] = 0.f;

    for (int kk = 0; kk < CDIM; kk += 32) {
        // Stage X tile: 128x32 floats = 1024 float4, tf32-rounded
        #pragma unroll
        for (int i = 0; i < 4; i++) {
            int idx = tid + i * 256;         // 0..1023
            int row = idx >> 3;
            int c4  = idx & 7;
            float4 v = *(const float4*)&x[(size_t)(r0 + row) * CDIM + kk + c4 * 4];
            uint4 u = { f2tf(v.x), f2tf(v.y), f2tf(v.z), f2tf(v.w) };
            *(uint4*)&Xs[row][c4 * 4] = u;
        }
        // Stage W tile: 32x64 floats = 512 float4
        #pragma unroll
        for (int i = 0; i < 2; i++) {
            int idx = tid + i * 256;         // 0..511
            int row = idx >> 4;
            int c4  = idx & 15;
            float4 v = *(const float4*)&W[(size_t)(kk + row) * CDIM + col0 + c4 * 4];
            uint4 u = { f2tf(v.x), f2tf(v.y), f2tf(v.z), f2tf(v.w) };
            *(uint4*)&Ws[row][c4 * 4] = u;
        }
        __syncthreads();

        #pragma unroll
        for (int ks = 0; ks < 4; ks++) {
            const int k = ks * 8;
            unsigned a[2][4], b[4][2];
            #pragma unroll
            for (int mi = 0; mi < 2; mi++) {
                int rb = wm + mi * 16 + g;
                a[mi][0] = Xs[rb][k + t];
                a[mi][1] = Xs[rb + 8][k + t];
                a[mi][2] = Xs[rb][k + t + 4];
                a[mi][3] = Xs[rb + 8][k + t + 4];
            }
            #pragma unroll
            for (int ni = 0; ni < 4; ni++) {
                int nc = wn + ni * 8 + g;
                b[ni][0] = Ws[k + t][nc];
                b[ni][1] = Ws[k + t + 4][nc];
            }
            #pragma unroll
            for (int mi = 0; mi < 2; mi++)
                #pragma unroll
                for (int ni = 0; ni < 4; ni++)
                    mma_tf32(acc[mi][ni], a[mi], b[ni]);
        }
        __syncthreads();
    }

    // Epilogue: bias + scatter to scratch in attention-friendly layout
    #pragma unroll
    for (int mi = 0; mi < 2; mi++) {
        #pragma unroll
        for (int ni = 0; ni < 4; ni++) {
            #pragma unroll
            for (int e = 0; e < 4; e++) {
                int row = wm + mi * 16 + g + ((e >= 2) ? 8 : 0);
                int col = wn + ni * 8 + t * 2 + (e & 1);
                int R  = r0 + row;
                int bm = R >> 9;
                int l  = R & 511;
                int c  = col0 + col;
                int h  = c >> 6;
                int d  = c & 63;
                float v = acc[mi][ni][e] + bias[c];
                if (mat == 0)
                    g_q[(((size_t)(bm * NH + h)) * LSEQ + l) * HD + d] = v;
                else if (mat == 1)
                    g_k[(((size_t)(bm * NH + h)) * LSEQ + l) * HD + d] = v;
                else
                    g_v[(((size_t)(bm * NH + h)) * HD + d) * LSEQ + l] = v;
            }
        }
    }
}

// ---------------------------------------------------------------------------
// Kernel 2: flash attention per (bm, h, q-tile of 128 rows). 256 threads.
// 8 warps x 16 q-rows. j-tiles of 128 keys. Online softmax in base 2.
// ---------------------------------------------------------------------------
#define QS_STRIDE 68
#define KS_STRIDE 68
#define VS_STRIDE 132
#define PS_STRIDE 132
#define SMEM_FLOATS (128*QS_STRIDE + 128*KS_STRIDE + 64*VS_STRIDE + 128*PS_STRIDE)
#define SMEM_BYTES  (SMEM_FLOATS * 4)

__global__ __launch_bounds__(256, 1) void attn_kernel(float* __restrict__ out)
{
    extern __shared__ unsigned smem[];
    unsigned* Qs = smem;                      // [128][68]  tf32
    unsigned* Ks = Qs + 128 * QS_STRIDE;      // [128][68]  tf32
    unsigned* Vs = Ks + 128 * KS_STRIDE;      // [64][132]  tf32 (d rows, l cols)
    unsigned* Ps = Vs + 64 * VS_STRIDE;       // [128][132] tf32

    const int qt = blockIdx.x;   // 0..3
    const int h  = blockIdx.y;   // 0..7
    const int bm = blockIdx.z;   // 0..63
    const int l0 = qt * 128;

    const int tid  = threadIdx.x;
    const int lane = tid & 31;
    const int warp = tid >> 5;
    const int g    = lane >> 2;
    const int t    = lane & 3;
    const int wr   = warp * 16;   // warp's q-row base within tile

    const float* qbase = g_q + ((size_t)(bm * NH + h)) * LSEQ * HD;
    const float* kbase = g_k + ((size_t)(bm * NH + h)) * LSEQ * HD;
    const float* vbase = g_v + ((size_t)(bm * NH + h)) * HD * LSEQ;

    // Stage Q tile (128x64) into smem, tf32-rounded
    #pragma unroll
    for (int i = 0; i < 8; i++) {
        int idx = tid + i * 256;       // 0..2047 float4
        int row = idx >> 4;
        int c4  = idx & 15;
        float4 v = *(const float4*)&qbase[(size_t)(l0 + row) * HD + c4 * 4];
        uint4 u = { f2tf(v.x), f2tf(v.y), f2tf(v.z), f2tf(v.w) };
        *(uint4*)&Qs[row * QS_STRIDE + c4 * 4] = u;
    }
    __syncthreads();

    // Register-resident Q fragments: 8 k-steps x 4 regs
    unsigned qa[8][4];
    #pragma unroll
    for (int ks = 0; ks < 8; ks++) {
        int kc = ks * 8 + t;
        int rb = wr + g;
        qa[ks][0] = Qs[rb * QS_STRIDE + kc];
        qa[ks][1] = Qs[(rb + 8) * QS_STRIDE + kc];
        qa[ks][2] = Qs[rb * QS_STRIDE + kc + 4];
        qa[ks][3] = Qs[(rb + 8) * QS_STRIDE + kc + 4];
    }

    float oacc[8][4];
    #pragma unroll
    for (int ni = 0; ni < 8; ni++)
        #pragma unroll
        for (int e = 0; e < 4; e++) oacc[ni][e] = 0.f;
    float mrow[2] = { -3.0e38f, -3.0e38f };   // running max (base-2 domain)
    float lsum[2] = { 0.f, 0.f };

    const float kInv = 1.4426950408889634f * 0.125f;  // log2(e) / sqrt(64)

    for (int j0 = 0; j0 < LSEQ; j0 += 128) {
        __syncthreads();   // previous iteration's smem reads complete
        // Stage K tile (128x64)
        #pragma unroll
        for (int i = 0; i < 8; i++) {
            int idx = tid + i * 256;
            int row = idx >> 4;
            int c4  = idx & 15;
            float4 v = *(const float4*)&kbase[(size_t)(j0 + row) * HD + c4 * 4];
            uint4 u = { f2tf(v.x), f2tf(v.y), f2tf(v.z), f2tf(v.w) };
            *(uint4*)&Ks[row * KS_STRIDE + c4 * 4] = u;
        }
        // Stage V^T tile (64 d-rows x 128 l-cols)
        #pragma unroll
        for (int i = 0; i < 8; i++) {
            int idx = tid + i * 256;
            int row = idx >> 5;        // d 0..63
            int c4  = idx & 31;
            float4 v = *(const float4*)&vbase[(size_t)row * LSEQ + j0 + c4 * 4];
            uint4 u = { f2tf(v.x), f2tf(v.y), f2tf(v.z), f2tf(v.w) };
            *(uint4*)&Vs[row * VS_STRIDE + c4 * 4] = u;
        }
        __syncthreads();

        // S = Q K^T for this warp's 16 rows x 128 cols
        float sacc[16][4];
        #pragma unroll
        for (int ni = 0; ni < 16; ni++)
            #pragma unroll
            for (int e = 0; e < 4; e++) sacc[ni][e] = 0.f;

        #pragma unroll
        for (int ks = 0; ks < 8; ks++) {
            #pragma unroll
            for (int ni = 0; ni < 16; ni++) {
                unsigned b[2];
                int nr = ni * 8 + g;
                b[0] = Ks[nr * KS_STRIDE + ks * 8 + t];
                b[1] = Ks[nr * KS_STRIDE + ks * 8 + t + 4];
                mma_tf32(sacc[ni], qa[ks], b);
            }
        }

        // Fold in scale * log2(e)
        #pragma unroll
        for (int ni = 0; ni < 16; ni++)
            #pragma unroll
            for (int e = 0; e < 4; e++) sacc[ni][e] *= kInv;

        // Online softmax per row-half (rh=0 -> rows g, rh=1 -> rows g+8)
        #pragma unroll
        for (int rh = 0; rh < 2; rh++) {
            float mt = -3.0e38f;
            #pragma unroll
            for (int ni = 0; ni < 16; ni++) {
                mt = fmaxf(mt, sacc[ni][2 * rh]);
                mt = fmaxf(mt, sacc[ni][2 * rh + 1]);
            }
            mt = fmaxf(mt, __shfl_xor_sync(0xffffffffu, mt, 1));
            mt = fmaxf(mt, __shfl_xor_sync(0xffffffffu, mt, 2));
            float mnew  = fmaxf(mrow[rh], mt);
            float alpha = exp2f(mrow[rh] - mnew);
            mrow[rh] = mnew;
            lsum[rh] *= alpha;
            #pragma unroll
            for (int ni = 0; ni < 8; ni++) {
                oacc[ni][2 * rh]     *= alpha;
                oacc[ni][2 * rh + 1] *= alpha;
            }
            float rs = 0.f;
            int prow = wr + g + rh * 8;
            #pragma unroll
            for (int ni = 0; ni < 16; ni++) {
                float p0 = exp2f(sacc[ni][2 * rh]     - mnew);
                float p1 = exp2f(sacc[ni][2 * rh + 1] - mnew);
                rs += p0 + p1;
                uint2 pv = { f2tf(p0), f2tf(p1) };
                *(uint2*)&Ps[prow * PS_STRIDE + ni * 8 + t * 2] = pv;
            }
            rs += __shfl_xor_sync(0xffffffffu, rs, 1);
            rs += __shfl_xor_sync(0xffffffffu, rs, 2);
            lsum[rh] += rs;
        }
        __syncwarp();   // Ps rows are warp-private; fence warp's smem stores

        // O += P V  (k over 128 keys, n over 64 dims)
        #pragma unroll
        for (int ks = 0; ks < 16; ks++) {
            unsigned a[4];
            int rb = wr + g;
            int kc = ks * 8 + t;
            a[0] = Ps[rb * PS_STRIDE + kc];
            a[1] = Ps[(rb + 8) * PS_STRIDE + kc];
            a[2] = Ps[rb * PS_STRIDE + kc + 4];
            a[3] = Ps[(rb + 8) * PS_STRIDE + kc + 4];
            #pragma unroll
            for (int ni = 0; ni < 8; ni++) {
                unsigned b[2];
                int dcol = ni * 8 + g;
                b[0] = Vs[dcol * VS_STRIDE + kc];
                b[1] = Vs[dcol * VS_STRIDE + kc + 4];
                mma_tf32(oacc[ni], a, b);
            }
        }
    }

    // Epilogue: normalize and write (B,M,L,C) layout
    float inv0 = 1.f / lsum[0];
    float inv1 = 1.f / lsum[1];
    #pragma unroll
    for (int rh = 0; rh < 2; rh++) {
        float inv = rh ? inv1 : inv0;
        int row = wr + g + rh * 8;
        int l   = l0 + row;
        #pragma unroll
        for (int ni = 0; ni < 8; ni++) {
            int c = h * HD + ni * 8 + t * 2;
            float2 o = { oacc[ni][2 * rh] * inv, oacc[ni][2 * rh + 1] * inv };
            *(float2*)&out[((size_t)bm * LSEQ + l) * CDIM + c] = o;
        }
    }
}

extern "C" void kernel_launch(void* const* d_in, const int* in_sizes, int n_in,
                              void* d_out, int out_size)
{
    const float* x  = (const float*)d_in[0];
    const float* Wq = (const float*)d_in[1];
    const float* bq = (const float*)d_in[2];
    const float* Wk = (const float*)d_in[3];
    const float* bk = (const float*)d_in[4];
    const float* Wv = (const float*)d_in[5];
    const float* bv = (const float*)d_in[6];
    float* out = (float*)d_out;

    qkv_kernel<<<dim3(24, 256), 256>>>(x, Wq, bq, Wk, bk, Wv, bv);

    cudaFuncSetAttribute(attn_kernel,
                         cudaFuncAttributeMaxDynamicSharedMemorySize, SMEM_BYTES);
    attn_kernel<<<dim3(4, NH, NBM), 256, SMEM_BYTES>>>(out);
}

// round 6
// speedup vs baseline: 1.2329x; 1.2329x over previous
#include <cuda_runtime.h>
#include <cuda_bf16.h>
#include <cstdint>

// Problem constants
#define NBM   64      // B*M = 2*32
#define LSEQ  512
#define CDIM  512
#define NH    8
#define HD    64

// Scratch: Q,K as [bm][h][l][d]; V transposed as [bm][h][d][l]; Wt as [3][n][k]
__device__ float g_q[NBM*NH*LSEQ*HD];
__device__ float g_k[NBM*NH*LSEQ*HD];
__device__ float g_v[NBM*NH*HD*LSEQ];
__device__ float g_wt[3*CDIM*CDIM];

__device__ __forceinline__ unsigned f2tf(float f) {
    unsigned u;
    asm("cvt.rna.tf32.f32 %0, %1;" : "=r"(u) : "f"(f));
    return u;
}

__device__ __forceinline__ void mma_tf32(float* c, const unsigned* a, const unsigned* b) {
    asm("mma.sync.aligned.m16n8k8.row.col.f32.tf32.tf32.f32 "
        "{%0,%1,%2,%3}, {%4,%5,%6,%7}, {%8,%9}, {%0,%1,%2,%3};"
        : "+f"(c[0]), "+f"(c[1]), "+f"(c[2]), "+f"(c[3])
        : "r"(a[0]), "r"(a[1]), "r"(a[2]), "r"(a[3]),
          "r"(b[0]), "r"(b[1]));
}

__device__ __forceinline__ uint32_t smem_u32(const void* p) {
    uint32_t a;
    asm("{ .reg .u64 t; cvta.to.shared.u64 t, %1; cvt.u32.u64 %0, t; }" : "=r"(a) : "l"(p));
    return a;
}

#define CP16(dst, src) \
    asm volatile("cp.async.cg.shared.global [%0], [%1], 16;" :: "r"(dst), "l"(src) : "memory")
#define CP_COMMIT() asm volatile("cp.async.commit_group;" ::: "memory")
#define CP_WAIT(n)  asm volatile("cp.async.wait_group %0;" :: "n"(n) : "memory")

// ---------------------------------------------------------------------------
// Pre-pass: Wt[mat][n][k] = rna_tf32(W[k][n])  (3 MB, ~3us)
// ---------------------------------------------------------------------------
__global__ __launch_bounds__(256) void wt_kernel(
    const float* __restrict__ Wq, const float* __restrict__ Wk,
    const float* __restrict__ Wv)
{
    __shared__ float s[32][33];
    const float* W = (blockIdx.z == 0) ? Wq : (blockIdx.z == 1) ? Wk : Wv;
    const int k0 = blockIdx.x * 32, n0 = blockIdx.y * 32;
    const int tid = threadIdx.x;
    {
        int kl = tid >> 3, n4 = tid & 7;
        float4 v = *(const float4*)&W[(size_t)(k0 + kl) * CDIM + n0 + n4 * 4];
        s[kl][n4 * 4 + 0] = __uint_as_float(f2tf(v.x));
        s[kl][n4 * 4 + 1] = __uint_as_float(f2tf(v.y));
        s[kl][n4 * 4 + 2] = __uint_as_float(f2tf(v.z));
        s[kl][n4 * 4 + 3] = __uint_as_float(f2tf(v.w));
    }
    __syncthreads();
    {
        int nl = tid >> 3, k4 = tid & 7;
        float4 o = { s[k4 * 4 + 0][nl], s[k4 * 4 + 1][nl],
                     s[k4 * 4 + 2][nl], s[k4 * 4 + 3][nl] };
        *(float4*)&g_wt[((size_t)(blockIdx.z * CDIM + n0 + nl)) * CDIM + k0 + k4 * 4] = o;
    }
}

// ---------------------------------------------------------------------------
// Kernel 1: QKV projection, mma.sync tf32, cp.async double-buffered.
// CTA tile 128x128, K=512 in 16 stages of 32. 8 warps, warp tile 64x32.
// Grid: (12 n-tiles, 256 m-tiles).
// ---------------------------------------------------------------------------
#define QKV_AST   36                    // padded floats per 32-wide row
#define QKV_ABF   (128*QKV_AST)         // floats per A (or B) tile
#define QKV_BUF   (2*QKV_ABF)           // floats per buffer (A + B)
#define QKV_SMEMB (2*QKV_BUF*4)         // bytes: 73728

__global__ __launch_bounds__(256, 2) void qkv_v2(
    const float* __restrict__ x,
    const float* __restrict__ bq, const float* __restrict__ bk,
    const float* __restrict__ bv)
{
    extern __shared__ float smem[];
    const uint32_t sbase = smem_u32(smem);

    const int tid  = threadIdx.x;
    const int lane = tid & 31;
    const int warp = tid >> 5;
    const int g    = lane >> 2;
    const int t    = lane & 3;
    const int wm   = (warp >> 2) * 64;   // warp row offset (0/64)
    const int wn   = (warp & 3) * 32;    // warp col offset (0/32/64/96)

    const int ntile = blockIdx.x;        // 0..11
    const int mat   = ntile >> 2;        // 0=Q,1=K,2=V
    const int col0  = (ntile & 3) * 128;
    const int r0    = blockIdx.y * 128;
    const float* bias = (mat == 0) ? bq : (mat == 1) ? bk : bv;

    // Per-thread staging pointers (8 cp.async of 16B per stage)
    const int srow = tid >> 3;           // 0..31 (+ i*32)
    const int sc4  = tid & 7;            // 16B column
    const float* xsrc = x + (size_t)(r0 + srow) * CDIM + sc4 * 4;
    const float* wsrc = g_wt + (size_t)(mat * CDIM + col0 + srow) * CDIM + sc4 * 4;
    const uint32_t sOff = (uint32_t)(srow * QKV_AST + sc4 * 4) * 4;

    // stage(kt, buf): A rows from x, B rows from g_wt
    auto stage = [&](int kt, int b) {
        const uint32_t aB = sbase + (uint32_t)b * (QKV_BUF * 4) + sOff;
        const uint32_t bB = aB + QKV_ABF * 4;
        const float* xs = xsrc + kt * 32;
        const float* ws = wsrc + kt * 32;
        #pragma unroll
        for (int i = 0; i < 4; i++) {
            CP16(aB + i * (32 * QKV_AST * 4), xs + (size_t)i * 32 * CDIM);
            CP16(bB + i * (32 * QKV_AST * 4), ws + (size_t)i * 32 * CDIM);
        }
        CP_COMMIT();
    };

    float acc[4][4][4];
    #pragma unroll
    for (int mi = 0; mi < 4; mi++)
        #pragma unroll
        for (int ni = 0; ni < 4; ni++)
            #pragma unroll
            for (int e = 0; e < 4; e++) acc[mi][ni][e] = 0.f;

    stage(0, 0);

    for (int kt = 0; kt < 16; kt++) {
        const int b = kt & 1;
        if (kt + 1 < 16) { stage(kt + 1, b ^ 1); CP_WAIT(1); }
        else             { CP_WAIT(0); }
        __syncthreads();

        const float*    As = smem + b * QKV_BUF;
        const unsigned* Bs = (const unsigned*)(smem + b * QKV_BUF + QKV_ABF);

        #pragma unroll
        for (int ks = 0; ks < 4; ks++) {
            const int k = ks * 8;
            unsigned a[4][4];
            #pragma unroll
            for (int mi = 0; mi < 4; mi++) {
                int rb = wm + mi * 16 + g;
                a[mi][0] = f2tf(As[rb * QKV_AST + k + t]);
                a[mi][1] = f2tf(As[(rb + 8) * QKV_AST + k + t]);
                a[mi][2] = f2tf(As[rb * QKV_AST + k + t + 4]);
                a[mi][3] = f2tf(As[(rb + 8) * QKV_AST + k + t + 4]);
            }
            #pragma unroll
            for (int ni = 0; ni < 4; ni++) {
                unsigned bfr[2];
                int nr = wn + ni * 8 + g;
                bfr[0] = Bs[nr * QKV_AST + k + t];
                bfr[1] = Bs[nr * QKV_AST + k + t + 4];
                #pragma unroll
                for (int mi = 0; mi < 4; mi++)
                    mma_tf32(acc[mi][ni], a[mi], bfr);
            }
        }
        __syncthreads();
    }

    // Epilogue: bias + scatter
    float bcol[4][2];
    #pragma unroll
    for (int ni = 0; ni < 4; ni++) {
        int c = col0 + wn + ni * 8 + t * 2;
        bcol[ni][0] = bias[c];
        bcol[ni][1] = bias[c + 1];
    }
    float* qk = (mat == 0) ? g_q : g_k;

    #pragma unroll
    for (int mi = 0; mi < 4; mi++) {
        #pragma unroll
        for (int ep = 0; ep < 2; ep++) {
            int row = wm + mi * 16 + g + ep * 8;
            int R = r0 + row;
            int bm = R >> 9, l = R & 511;
            #pragma unroll
            for (int ni = 0; ni < 4; ni++) {
                int c = col0 + wn + ni * 8 + t * 2;
                int h = c >> 6, d = c & 63;
                float v0 = acc[mi][ni][2 * ep]     + bcol[ni][0];
                float v1 = acc[mi][ni][2 * ep + 1] + bcol[ni][1];
                if (mat < 2) {
                    float2 o = { v0, v1 };
                    *(float2*)&qk[(((size_t)(bm * NH + h)) * LSEQ + l) * HD + d] = o;
                } else {
                    size_t base = ((size_t)(bm * NH + h)) * HD;
                    g_v[(base + d)     * LSEQ + l] = v0;
                    g_v[(base + d + 1) * LSEQ + l] = v1;
                }
            }
        }
    }
}

// ---------------------------------------------------------------------------
// Kernel 2: flash attention per (bm, h, q-tile of 128 rows). 256 threads.
// (unchanged from the round-1 passing version)
// ---------------------------------------------------------------------------
#define QS_STRIDE 68
#define KS_STRIDE 68
#define VS_STRIDE 132
#define PS_STRIDE 132
#define SMEM_FLOATS (128*QS_STRIDE + 128*KS_STRIDE + 64*VS_STRIDE + 128*PS_STRIDE)
#define SMEM_BYTES  (SMEM_FLOATS * 4)

__global__ __launch_bounds__(256, 1) void attn_kernel(float* __restrict__ out)
{
    extern __shared__ unsigned asmem[];
    unsigned* Qs = asmem;
    unsigned* Ks = Qs + 128 * QS_STRIDE;
    unsigned* Vs = Ks + 128 * KS_STRIDE;
    unsigned* Ps = Vs + 64 * VS_STRIDE;

    const int qt = blockIdx.x;
    const int h  = blockIdx.y;
    const int bm = blockIdx.z;
    const int l0 = qt * 128;

    const int tid  = threadIdx.x;
    const int lane = tid & 31;
    const int warp = tid >> 5;
    const int g    = lane >> 2;
    const int t    = lane & 3;
    const int wr   = warp * 16;

    const float* qbase = g_q + ((size_t)(bm * NH + h)) * LSEQ * HD;
    const float* kbase = g_k + ((size_t)(bm * NH + h)) * LSEQ * HD;
    const float* vbase = g_v + ((size_t)(bm * NH + h)) * HD * LSEQ;

    #pragma unroll
    for (int i = 0; i < 8; i++) {
        int idx = tid + i * 256;
        int row = idx >> 4;
        int c4  = idx & 15;
        float4 v = *(const float4*)&qbase[(size_t)(l0 + row) * HD + c4 * 4];
        uint4 u = { f2tf(v.x), f2tf(v.y), f2tf(v.z), f2tf(v.w) };
        *(uint4*)&Qs[row * QS_STRIDE + c4 * 4] = u;
    }
    __syncthreads();

    unsigned qa[8][4];
    #pragma unroll
    for (int ks = 0; ks < 8; ks++) {
        int kc = ks * 8 + t;
        int rb = wr + g;
        qa[ks][0] = Qs[rb * QS_STRIDE + kc];
        qa[ks][1] = Qs[(rb + 8) * QS_STRIDE + kc];
        qa[ks][2] = Qs[rb * QS_STRIDE + kc + 4];
        qa[ks][3] = Qs[(rb + 8) * QS_STRIDE + kc + 4];
    }

    float oacc[8][4];
    #pragma unroll
    for (int ni = 0; ni < 8; ni++)
        #pragma unroll
        for (int e = 0; e < 4; e++) oacc[ni][e] = 0.f;
    float mrow[2] = { -3.0e38f, -3.0e38f };
    float lsum[2] = { 0.f, 0.f };

    const float kInv = 1.4426950408889634f * 0.125f;

    for (int j0 = 0; j0 < LSEQ; j0 += 128) {
        __syncthreads();
        #pragma unroll
        for (int i = 0; i < 8; i++) {
            int idx = tid + i * 256;
            int row = idx >> 4;
            int c4  = idx & 15;
            float4 v = *(const float4*)&kbase[(size_t)(j0 + row) * HD + c4 * 4];
            uint4 u = { f2tf(v.x), f2tf(v.y), f2tf(v.z), f2tf(v.w) };
            *(uint4*)&Ks[row * KS_STRIDE + c4 * 4] = u;
        }
        #pragma unroll
        for (int i = 0; i < 8; i++) {
            int idx = tid + i * 256;
            int row = idx >> 5;
            int c4  = idx & 31;
            float4 v = *(const float4*)&vbase[(size_t)row * LSEQ + j0 + c4 * 4];
            uint4 u = { f2tf(v.x), f2tf(v.y), f2tf(v.z), f2tf(v.w) };
            *(uint4*)&Vs[row * VS_STRIDE + c4 * 4] = u;
        }
        __syncthreads();

        float sacc[16][4];
        #pragma unroll
        for (int ni = 0; ni < 16; ni++)
            #pragma unroll
            for (int e = 0; e < 4; e++) sacc[ni][e] = 0.f;

        #pragma unroll
        for (int ks = 0; ks < 8; ks++) {
            #pragma unroll
            for (int ni = 0; ni < 16; ni++) {
                unsigned b[2];
                int nr = ni * 8 + g;
                b[0] = Ks[nr * KS_STRIDE + ks * 8 + t];
                b[1] = Ks[nr * KS_STRIDE + ks * 8 + t + 4];
                mma_tf32(sacc[ni], qa[ks], b);
            }
        }

        #pragma unroll
        for (int ni = 0; ni < 16; ni++)
            #pragma unroll
            for (int e = 0; e < 4; e++) sacc[ni][e] *= kInv;

        #pragma unroll
        for (int rh = 0; rh < 2; rh++) {
            float mt = -3.0e38f;
            #pragma unroll
            for (int ni = 0; ni < 16; ni++) {
                mt = fmaxf(mt, sacc[ni][2 * rh]);
                mt = fmaxf(mt, sacc[ni][2 * rh + 1]);
            }
            mt = fmaxf(mt, __shfl_xor_sync(0xffffffffu, mt, 1));
            mt = fmaxf(mt, __shfl_xor_sync(0xffffffffu, mt, 2));
            float mnew  = fmaxf(mrow[rh], mt);
            float alpha = exp2f(mrow[rh] - mnew);
            mrow[rh] = mnew;
            lsum[rh] *= alpha;
            #pragma unroll
            for (int ni = 0; ni < 8; ni++) {
                oacc[ni][2 * rh]     *= alpha;
                oacc[ni][2 * rh + 1] *= alpha;
            }
            float rs = 0.f;
            int prow = wr + g + rh * 8;
            #pragma unroll
            for (int ni = 0; ni < 16; ni++) {
                float p0 = exp2f(sacc[ni][2 * rh]     - mnew);
                float p1 = exp2f(sacc[ni][2 * rh + 1] - mnew);
                rs += p0 + p1;
                uint2 pv = { f2tf(p0), f2tf(p1) };
                *(uint2*)&Ps[prow * PS_STRIDE + ni * 8 + t * 2] = pv;
            }
            rs += __shfl_xor_sync(0xffffffffu, rs, 1);
            rs += __shfl_xor_sync(0xffffffffu, rs, 2);
            lsum[rh] += rs;
        }
        __syncwarp();

        #pragma unroll
        for (int ks = 0; ks < 16; ks++) {
            unsigned a[4];
            int rb = wr + g;
            int kc = ks * 8 + t;
            a[0] = Ps[rb * PS_STRIDE + kc];
            a[1] = Ps[(rb + 8) * PS_STRIDE + kc];
            a[2] = Ps[rb * PS_STRIDE + kc + 4];
            a[3] = Ps[(rb + 8) * PS_STRIDE + kc + 4];
            #pragma unroll
            for (int ni = 0; ni < 8; ni++) {
                unsigned b[2];
                int dcol = ni * 8 + g;
                b[0] = Vs[dcol * VS_STRIDE + kc];
                b[1] = Vs[dcol * VS_STRIDE + kc + 4];
                mma_tf32(oacc[ni], a, b);
            }
        }
    }

    float inv0 = 1.f / lsum[0];
    float inv1 = 1.f / lsum[1];
    #pragma unroll
    for (int rh = 0; rh < 2; rh++) {
        float inv = rh ? inv1 : inv0;
        int row = wr + g + rh * 8;
        int l   = l0 + row;
        #pragma unroll
        for (int ni = 0; ni < 8; ni++) {
            int c = h * HD + ni * 8 + t * 2;
            float2 o = { oacc[ni][2 * rh] * inv, oacc[ni][2 * rh + 1] * inv };
            *(float2*)&out[((size_t)bm * LSEQ + l) * CDIM + c] = o;
        }
    }
}

extern "C" void kernel_launch(void* const* d_in, const int* in_sizes, int n_in,
                              void* d_out, int out_size)
{
    const float* x  = (const float*)d_in[0];
    const float* Wq = (const float*)d_in[1];
    const float* bq = (const float*)d_in[2];
    const float* Wk = (const float*)d_in[3];
    const float* bk = (const float*)d_in[4];
    const float* Wv = (const float*)d_in[5];
    const float* bv = (const float*)d_in[6];
    float* out = (float*)d_out;

    wt_kernel<<<dim3(16, 16, 3), 256>>>(Wq, Wk, Wv);

    cudaFuncSetAttribute(qkv_v2,
                         cudaFuncAttributeMaxDynamicSharedMemorySize, QKV_SMEMB);
    qkv_v2<<<dim3(12, 256), 256, QKV_SMEMB>>>(x, bq, bk, bv);

    cudaFuncSetAttribute(attn_kernel,
                         cudaFuncAttributeMaxDynamicSharedMemorySize, SMEM_BYTES);
    attn_kernel<<<dim3(4, NH, NBM), 256, SMEM_BYTES>>>(out);
}

// round 7
// speedup vs baseline: 1.3477x; 1.0931x over previous
#include <cuda_runtime.h>
#include <cuda_bf16.h>
#include <cstdint>

// Problem constants
#define NBM   64      // B*M = 2*32
#define LSEQ  512
#define CDIM  512
#define NH    8
#define HD    64
#define NROWS (NBM*LSEQ)   // 32768

// Scratch (all tf32-rounded, k-dims permuted within 8-groups):
//  g_xt: X rows with permuted k           [32768][512]
//  g_q,g_k: [bm][h][l][d'] (d permuted)
//  g_v: [bm][h][d][l'] (l permuted)
//  g_wt: [3][n][k'] (k permuted)
__device__ float g_xt[NROWS*CDIM];
__device__ float g_q[NBM*NH*LSEQ*HD];
__device__ float g_k[NBM*NH*LSEQ*HD];
__device__ float g_v[NBM*NH*HD*LSEQ];
__device__ float g_wt[3*CDIM*CDIM];

// perm within 8: v -> ((v&3)<<1)|(v>>2)  == {0,2,4,6,1,3,5,7}
__device__ __forceinline__ int perm8(int v) { return ((v & 3) << 1) | (v >> 2); }

__device__ __forceinline__ unsigned f2tf(float f) {
    unsigned u;
    asm("cvt.rna.tf32.f32 %0, %1;" : "=r"(u) : "f"(f));
    return u;
}
__device__ __forceinline__ float f2tff(float f) { return __uint_as_float(f2tf(f)); }

__device__ __forceinline__ void mma_tf32(float* c, const unsigned* a, const unsigned* b) {
    asm("mma.sync.aligned.m16n8k8.row.col.f32.tf32.tf32.f32 "
        "{%0,%1,%2,%3}, {%4,%5,%6,%7}, {%8,%9}, {%0,%1,%2,%3};"
        : "+f"(c[0]), "+f"(c[1]), "+f"(c[2]), "+f"(c[3])
        : "r"(a[0]), "r"(a[1]), "r"(a[2]), "r"(a[3]),
          "r"(b[0]), "r"(b[1]));
}

__device__ __forceinline__ uint32_t smem_u32(const void* p) {
    uint32_t a;
    asm("{ .reg .u64 t; cvta.to.shared.u64 t, %1; cvt.u32.u64 %0, t; }" : "=r"(a) : "l"(p));
    return a;
}

#define CP16(dst, src) \
    asm volatile("cp.async.cg.shared.global [%0], [%1], 16;" :: "r"(dst), "l"(src) : "memory")
#define CP_COMMIT() asm volatile("cp.async.commit_group;" ::: "memory")
#define CP_WAIT(n)  asm volatile("cp.async.wait_group %0;" :: "n"(n) : "memory")

// ---------------------------------------------------------------------------
// Pre-pass A: g_xt = rna_tf32(x) with k permuted within 8-groups.
// ---------------------------------------------------------------------------
__global__ __launch_bounds__(256) void xt_kernel(const float* __restrict__ x)
{
    int idx = blockIdx.x * 256 + threadIdx.x;          // float4 index
    float4 v = ((const float4*)x)[idx];
    int fbase = idx * 4;
    int grp   = fbase & ~7;
    int start = (fbase >> 2) & 1;                      // 0 for lower half, 1 for upper
    float* dst = g_xt + grp + start;
    dst[0] = f2tff(v.x);
    dst[2] = f2tff(v.y);
    dst[4] = f2tff(v.z);
    dst[6] = f2tff(v.w);
}

// ---------------------------------------------------------------------------
// Pre-pass B: Wt[mat][n][k'] = rna_tf32(W[k][n]), k permuted within 8.
// ---------------------------------------------------------------------------
__global__ __launch_bounds__(256) void wt_kernel(
    const float* __restrict__ Wq, const float* __restrict__ Wk,
    const float* __restrict__ Wv)
{
    __shared__ float s[32][33];
    const float* W = (blockIdx.z == 0) ? Wq : (blockIdx.z == 1) ? Wk : Wv;
    const int k0 = blockIdx.x * 32, n0 = blockIdx.y * 32;
    const int tid = threadIdx.x;
    {
        int kl = tid >> 3, n4 = tid & 7;
        float4 v = *(const float4*)&W[(size_t)(k0 + kl) * CDIM + n0 + n4 * 4];
        s[kl][n4 * 4 + 0] = f2tff(v.x);
        s[kl][n4 * 4 + 1] = f2tff(v.y);
        s[kl][n4 * 4 + 2] = f2tff(v.z);
        s[kl][n4 * 4 + 3] = f2tff(v.w);
    }
    __syncthreads();
    {
        int nl = tid >> 3, k4 = tid & 7;
        float* rowp = g_wt + ((size_t)(blockIdx.z * CDIM + n0 + nl)) * CDIM;
        #pragma unroll
        for (int j = 0; j < 4; j++) {
            int kk = k0 + k4 * 4 + j;
            int kp = (kk & ~7) | perm8(kk & 7);
            rowp[kp] = s[k4 * 4 + j][nl];
        }
    }
}

// ---------------------------------------------------------------------------
// Kernel 1: QKV projection, mma.sync tf32, cp.async double-buffered.
// CTA tile 128x128, K=512 in 16 stages of 32. 8 warps, warp tile 64x32.
// All operands pre-rounded + pre-permuted -> LDS.64 fragment loads, no cvt.
// ---------------------------------------------------------------------------
#define QKV_AST   40                    // floats per 32-wide row (40%32==8)
#define QKV_ABF   (128*QKV_AST)         // floats per A (or B) tile: 5120
#define QKV_BUF   (2*QKV_ABF)           // floats per buffer (A + B): 10240
#define QKV_SMEMB (2*QKV_BUF*4)         // bytes: 81920

__global__ __launch_bounds__(256, 2) void qkv_v3(
    const float* __restrict__ bq, const float* __restrict__ bk,
    const float* __restrict__ bv)
{
    extern __shared__ float smem[];
    const uint32_t sbase = smem_u32(smem);

    const int tid  = threadIdx.x;
    const int lane = tid & 31;
    const int warp = tid >> 5;
    const int g    = lane >> 2;
    const int t    = lane & 3;
    const int wm   = (warp >> 2) * 64;   // warp row offset (0/64)
    const int wn   = (warp & 3) * 32;    // warp col offset (0/32/64/96)

    const int ntile = blockIdx.x;        // 0..11
    const int mat   = ntile >> 2;        // 0=Q,1=K,2=V
    const int col0  = (ntile & 3) * 128;
    const int r0    = blockIdx.y * 128;
    const float* bias = (mat == 0) ? bq : (mat == 1) ? bk : bv;

    // Staging pointers (8 cp.async of 16B per thread per stage)
    const int srow = tid >> 3;           // 0..31 (+ i*32)
    const int sc4  = tid & 7;
    const float* xsrc = g_xt + (size_t)(r0 + srow) * CDIM + sc4 * 4;
    const float* wsrc = g_wt + (size_t)(mat * CDIM + col0 + srow) * CDIM + sc4 * 4;
    const uint32_t sOff = (uint32_t)(srow * QKV_AST + sc4 * 4) * 4;

    auto stage = [&](int kt, int b) {
        const uint32_t aB = sbase + (uint32_t)b * (QKV_BUF * 4) + sOff;
        const uint32_t bB = aB + QKV_ABF * 4;
        const float* xs = xsrc + kt * 32;
        const float* ws = wsrc + kt * 32;
        #pragma unroll
        for (int i = 0; i < 4; i++) {
            CP16(aB + i * (32 * QKV_AST * 4), xs + (size_t)i * 32 * CDIM);
            CP16(bB + i * (32 * QKV_AST * 4), ws + (size_t)i * 32 * CDIM);
        }
        CP_COMMIT();
    };

    float acc[4][4][4];
    #pragma unroll
    for (int mi = 0; mi < 4; mi++)
        #pragma unroll
        for (int ni = 0; ni < 4; ni++)
            #pragma unroll
            for (int e = 0; e < 4; e++) acc[mi][ni][e] = 0.f;

    stage(0, 0);

    for (int kt = 0; kt < 16; kt++) {
        const int b = kt & 1;
        if (kt + 1 < 16) { stage(kt + 1, b ^ 1); CP_WAIT(1); }
        else             { CP_WAIT(0); }
        __syncthreads();

        const unsigned* As = (const unsigned*)(smem + b * QKV_BUF);
        const unsigned* Bs = (const unsigned*)(smem + b * QKV_BUF + QKV_ABF);

        #pragma unroll
        for (int ks = 0; ks < 4; ks++) {
            const int k2 = ks * 8 + 2 * t;      // permuted: holds {k+t, k+t+4}
            unsigned a[4][4];
            #pragma unroll
            for (int mi = 0; mi < 4; mi++) {
                int rb = wm + mi * 16 + g;
                uint2 lo = *(const uint2*)&As[rb * QKV_AST + k2];
                uint2 hi = *(const uint2*)&As[(rb + 8) * QKV_AST + k2];
                a[mi][0] = lo.x; a[mi][1] = hi.x; a[mi][2] = lo.y; a[mi][3] = hi.y;
            }
            #pragma unroll
            for (int ni = 0; ni < 4; ni++) {
                int nr = wn + ni * 8 + g;
                uint2 b2 = *(const uint2*)&Bs[nr * QKV_AST + k2];
                unsigned bfr[2] = { b2.x, b2.y };
                #pragma unroll
                for (int mi = 0; mi < 4; mi++)
                    mma_tf32(acc[mi][ni], a[mi], bfr);
            }
        }
        __syncthreads();
    }

    // Epilogue: bias + tf32 round + permuted scatter
    float bcol[4][2];
    #pragma unroll
    for (int ni = 0; ni < 4; ni++) {
        int c = col0 + wn + ni * 8 + t * 2;
        bcol[ni][0] = bias[c];
        bcol[ni][1] = bias[c + 1];
    }
    float* qk = (mat == 0) ? g_q : g_k;
    const int pc0 = ((t & 1) << 2) | (t >> 1);   // perm8(2t) = {0,4,1,5}

    #pragma unroll
    for (int mi = 0; mi < 4; mi++) {
        #pragma unroll
        for (int ep = 0; ep < 2; ep++) {
            int row = wm + mi * 16 + g + ep * 8;
            int R = r0 + row;
            int bm = R >> 9, l = R & 511;
            int lp = (l & ~7) + perm8(g);        // l&7 == g here
            #pragma unroll
            for (int ni = 0; ni < 4; ni++) {
                int c = col0 + wn + ni * 8 + t * 2;
                int h = c >> 6, d = c & 63;
                float v0 = f2tff(acc[mi][ni][2 * ep]     + bcol[ni][0]);
                float v1 = f2tff(acc[mi][ni][2 * ep + 1] + bcol[ni][1]);
                if (mat < 2) {
                    // d&7 == 2t -> permuted positions pc0, pc0+2
                    float* base = qk + (((size_t)(bm * NH + h)) * LSEQ + l) * HD + (d & ~7);
                    base[pc0]     = v0;
                    base[pc0 + 2] = v1;
                } else {
                    size_t base = ((size_t)(bm * NH + h)) * HD;
                    g_v[(base + d)     * LSEQ + lp] = v0;
                    g_v[(base + d + 1) * LSEQ + lp] = v1;
                }
            }
        }
    }
}

// ---------------------------------------------------------------------------
// Kernel 2: flash attention per (bm, h, q-tile of 128 rows). 256 threads.
// cp.async double-buffered K/V, LDS.64 fragments, no cvts in the loop.
// smem: Ks[2][128][72] | Vs[2][64][136] | Ps[128][136] (Q staged in Ps region)
// ---------------------------------------------------------------------------
#define KST 72
#define VST 136
#define PST 136
#define KS_OFF(b) ((b) * 128 * KST)                 // floats
#define VS_OFF(b) (2 * 128 * KST + (b) * 64 * VST)
#define PS_OFF    (2 * 128 * KST + 2 * 64 * VST)
#define ATTN_FLOATS (PS_OFF + 128 * PST)
#define ATTN_SMEMB  (ATTN_FLOATS * 4)               // 212992 bytes

__global__ __launch_bounds__(256, 1) void attn_kernel(float* __restrict__ out)
{
    extern __shared__ float asmem[];
    const uint32_t sbase = smem_u32(asmem);
    const unsigned* Ps = (const unsigned*)(asmem + PS_OFF);
    float* Psw = asmem + PS_OFF;

    const int qt = blockIdx.x;
    const int h  = blockIdx.y;
    const int bm = blockIdx.z;
    const int l0 = qt * 128;

    const int tid  = threadIdx.x;
    const int lane = tid & 31;
    const int warp = tid >> 5;
    const int g    = lane >> 2;
    const int t    = lane & 3;
    const int wr   = warp * 16;

    const float* qb = g_q + ((size_t)(bm * NH + h)) * LSEQ * HD;
    const float* kb = g_k + ((size_t)(bm * NH + h)) * LSEQ * HD;
    const float* vb = g_v + ((size_t)(bm * NH + h)) * HD * LSEQ;

    // staging index splits
    const int qrow = tid >> 1, qc16 = tid & 1;      // for 128x64 tiles: 8 chunks/row
    const int vrow = tid >> 2, vc16 = tid & 3;      // for 64x128 tiles: 32 chunks/row

    auto stage_k = [&](int j0, int b) {
        const float* src = kb + (size_t)(j0 + qrow) * HD + qc16 * 16;
        uint32_t dst = sbase + (KS_OFF(b) + qrow * KST + qc16 * 16) * 4;
        #pragma unroll
        for (int i = 0; i < 4; i++)
            CP16(dst + i * 32 * 4, src + i * 8);    // 4 chunks of 16B stride 32 floats? no:
    };
    // NOTE: lambda above replaced below by explicit loops (kept simple & correct)

    // ---- stage Q (into Ps region, stride KST) + K0 + V0 ----
    #pragma unroll
    for (int i = 0; i < 8; i++) {
        int idx = tid + i * 256;                    // 0..2047 chunks of 16B
        int row = idx >> 4, c16 = idx & 15;
        uint32_t dst = sbase + (uint32_t)(PS_OFF + row * KST + c16 * 4) * 4;
        CP16(dst, qb + (size_t)(l0 + row) * HD + c16 * 4);
    }
    #pragma unroll
    for (int i = 0; i < 8; i++) {
        int idx = tid + i * 256;
        int row = idx >> 4, c16 = idx & 15;
        uint32_t dst = sbase + (uint32_t)(KS_OFF(0) + row * KST + c16 * 4) * 4;
        CP16(dst, kb + (size_t)row * HD + c16 * 4);
    }
    #pragma unroll
    for (int i = 0; i < 8; i++) {
        int idx = tid + i * 256;
        int row = idx >> 5, c32 = idx & 31;
        uint32_t dst = sbase + (uint32_t)(VS_OFF(0) + row * VST + c32 * 4) * 4;
        CP16(dst, vb + (size_t)row * LSEQ + c32 * 4);
    }
    CP_COMMIT();
    CP_WAIT(0);
    __syncthreads();

    // ---- extract Q fragments (Q region will be overwritten by Ps) ----
    unsigned qa[8][4];
    #pragma unroll
    for (int ks = 0; ks < 8; ks++) {
        int k2 = ks * 8 + 2 * t;
        const unsigned* Q = (const unsigned*)(asmem + PS_OFF);
        uint2 lo = *(const uint2*)&Q[(wr + g) * KST + k2];
        uint2 hi = *(const uint2*)&Q[(wr + g + 8) * KST + k2];
        qa[ks][0] = lo.x; qa[ks][1] = hi.x; qa[ks][2] = lo.y; qa[ks][3] = hi.y;
    }
    __syncwarp();

    float oacc[8][4];
    #pragma unroll
    for (int ni = 0; ni < 8; ni++)
        #pragma unroll
        for (int e = 0; e < 4; e++) oacc[ni][e] = 0.f;
    float mrow[2] = { -3.0e38f, -3.0e38f };
    float lsum[2] = { 0.f, 0.f };

    const float kInv = 1.4426950408889634f * 0.125f;  // log2(e)/sqrt(64)
    const int pc0 = ((t & 1) << 2) | (t >> 1);         // perm8(2t)

    for (int j = 0; j < 4; j++) {
        const int b = j & 1;
        // prefetch next K/V tile
        if (j < 3) {
            const int jn = (j + 1) * 128;
            #pragma unroll
            for (int i = 0; i < 8; i++) {
                int idx = tid + i * 256;
                int row = idx >> 4, c16 = idx & 15;
                uint32_t dst = sbase + (uint32_t)(KS_OFF(b ^ 1) + row * KST + c16 * 4) * 4;
                CP16(dst, kb + (size_t)(jn + row) * HD + c16 * 4);
            }
            #pragma unroll
            for (int i = 0; i < 8; i++) {
                int idx = tid + i * 256;
                int row = idx >> 5, c32 = idx & 31;
                uint32_t dst = sbase + (uint32_t)(VS_OFF(b ^ 1) + row * VST + c32 * 4) * 4;
                CP16(dst, vb + (size_t)row * LSEQ + jn + c32 * 4);
            }
            CP_COMMIT();
        }

        const unsigned* Ks = (const unsigned*)(asmem + KS_OFF(b));
        const unsigned* Vs = (const unsigned*)(asmem + VS_OFF(b));

        // S = Q K^T
        float sacc[16][4];
        #pragma unroll
        for (int ni = 0; ni < 16; ni++)
            #pragma unroll
            for (int e = 0; e < 4; e++) sacc[ni][e] = 0.f;

        #pragma unroll
        for (int ks = 0; ks < 8; ks++) {
            const int k2 = ks * 8 + 2 * t;
            #pragma unroll
            for (int ni = 0; ni < 16; ni++) {
                uint2 b2 = *(const uint2*)&Ks[(ni * 8 + g) * KST + k2];
                unsigned bfr[2] = { b2.x, b2.y };
                mma_tf32(sacc[ni], qa[ks], bfr);
            }
        }

        #pragma unroll
        for (int ni = 0; ni < 16; ni++)
            #pragma unroll
            for (int e = 0; e < 4; e++) sacc[ni][e] *= kInv;

        // online softmax (base 2), P stored permuted
        #pragma unroll
        for (int rh = 0; rh < 2; rh++) {
            float mt = -3.0e38f;
            #pragma unroll
            for (int ni = 0; ni < 16; ni++) {
                mt = fmaxf(mt, sacc[ni][2 * rh]);
                mt = fmaxf(mt, sacc[ni][2 * rh + 1]);
            }
            mt = fmaxf(mt, __shfl_xor_sync(0xffffffffu, mt, 1));
            mt = fmaxf(mt, __shfl_xor_sync(0xffffffffu, mt, 2));
            float mnew  = fmaxf(mrow[rh], mt);
            float alpha = exp2f(mrow[rh] - mnew);
            mrow[rh] = mnew;
            lsum[rh] *= alpha;
            #pragma unroll
            for (int ni = 0; ni < 8; ni++) {
                oacc[ni][2 * rh]     *= alpha;
                oacc[ni][2 * rh + 1] *= alpha;
            }
            float rs = 0.f;
            int prow = wr + g + rh * 8;
            #pragma unroll
            for (int ni = 0; ni < 16; ni++) {
                float p0 = exp2f(sacc[ni][2 * rh]     - mnew);
                float p1 = exp2f(sacc[ni][2 * rh + 1] - mnew);
                rs += p0 + p1;
                Psw[prow * PST + ni * 8 + pc0]     = f2tff(p0);
                Psw[prow * PST + ni * 8 + pc0 + 2] = f2tff(p1);
            }
            rs += __shfl_xor_sync(0xffffffffu, rs, 1);
            rs += __shfl_xor_sync(0xffffffffu, rs, 2);
            lsum[rh] += rs;
        }
        __syncwarp();

        // O += P V
        #pragma unroll
        for (int ks = 0; ks < 16; ks++) {
            const int k2 = ks * 8 + 2 * t;
            uint2 aL = *(const uint2*)&Ps[(wr + g) * PST + k2];
            uint2 aH = *(const uint2*)&Ps[(wr + g + 8) * PST + k2];
            unsigned a[4] = { aL.x, aH.x, aL.y, aH.y };
            #pragma unroll
            for (int ni = 0; ni < 8; ni++) {
                uint2 b2 = *(const uint2*)&Vs[(ni * 8 + g) * VST + k2];
                unsigned bfr[2] = { b2.x, b2.y };
                mma_tf32(oacc[ni], a, bfr);
            }
        }

        if (j < 3) { CP_WAIT(0); __syncthreads(); }
    }

    // epilogue: normalize + write (B,M,L,C)
    float inv0 = 1.f / lsum[0];
    float inv1 = 1.f / lsum[1];
    #pragma unroll
    for (int rh = 0; rh < 2; rh++) {
        float inv = rh ? inv1 : inv0;
        int row = wr + g + rh * 8;
        int l   = l0 + row;
        #pragma unroll
        for (int ni = 0; ni < 8; ni++) {
            int c = h * HD + ni * 8 + t * 2;
            float2 o = { oacc[ni][2 * rh] * inv, oacc[ni][2 * rh + 1] * inv };
            *(float2*)&out[((size_t)bm * LSEQ + l) * CDIM + c] = o;
        }
    }
}

extern "C" void kernel_launch(void* const* d_in, const int* in_sizes, int n_in,
                              void* d_out, int out_size)
{
    const float* x  = (const float*)d_in[0];
    const float* Wq = (const float*)d_in[1];
    const float* bq = (const float*)d_in[2];
    const float* Wk = (const float*)d_in[3];
    const float* bk = (const float*)d_in[4];
    const float* Wv = (const float*)d_in[5];
    const float* bv = (const float*)d_in[6];
    float* out = (float*)d_out;

    xt_kernel<<<NROWS * CDIM / 4 / 256, 256>>>(x);
    wt_kernel<<<dim3(16, 16, 3), 256>>>(Wq, Wk, Wv);

    cudaFuncSetAttribute(qkv_v3,
                         cudaFuncAttributeMaxDynamicSharedMemorySize, QKV_SMEMB);
    qkv_v3<<<dim3(12, 256), 256, QKV_SMEMB>>>(bq, bk, bv);

    cudaFuncSetAttribute(attn_kernel,
                         cudaFuncAttributeMaxDynamicSharedMemorySize, ATTN_SMEMB);
    attn_kernel<<<dim3(4, NH, NBM), 256, ATTN_SMEMB>>>(out);
}